// round 14
// baseline (speedup 1.0000x reference)
#include <cuda_runtime.h>
#include <cstdint>

#define N_NODES  50000
#define N_EDGES  800000
#define N_GRAPHS 256
#define D_FEAT   96
#define HIDDEN   32

#define XS_STRIDE 100   // 96 + 4 pad floats
#define HS_STRIDE 36    // 32 + 4 pad

// Scratch (no cudaMalloc allowed)
__device__ float g_y[N_NODES * HIDDEN];     // x @ W1 (clean copy, k2 gather src)
__device__ float g_agg[N_NODES * HIDDEN];   // accumulator, initialized to y
__device__ float g_pool[N_GRAPHS * HIDDEN]; // per-graph sums
__device__ float g_cnt[N_GRAPHS];           // per-graph node counts
__device__ unsigned g_done;                 // k3 completion counter

// ---------------- f32x2 helpers ----------------
__device__ __forceinline__ unsigned long long pk2(float lo, float hi) {
    unsigned long long r;
    asm("mov.b64 %0, {%1, %2};" : "=l"(r) : "f"(lo), "f"(hi));
    return r;
}
__device__ __forceinline__ void ffma2(unsigned long long& acc,
                                      unsigned long long a, unsigned long long b) {
    asm("fma.rn.f32x2 %0, %1, %2, %0;" : "+l"(acc) : "l"(a), "l"(b));
}
__device__ __forceinline__ float2 up2(unsigned long long v) {
    float2 r;
    asm("mov.b64 {%0, %1}, %2;" : "=f"(r.x), "=f"(r.y) : "l"(v));
    return r;
}
// ---------------- cp.async helpers ----------------
__device__ __forceinline__ void cpa16(uint32_t smem_dst, const void* gmem_src) {
    asm volatile("cp.async.cg.shared.global [%0], [%1], 16;"
                 :: "r"(smem_dst), "l"(gmem_src));
}
__device__ __forceinline__ void cpa_commit_wait() {
    asm volatile("cp.async.commit_group;");
    asm volatile("cp.async.wait_group 0;");
}
// ---------------- PDL helpers ----------------
__device__ __forceinline__ void pdl_wait() {
    asm volatile("griddepcontrol.wait;" ::: "memory");
}
__device__ __forceinline__ void pdl_trigger() {
    asm volatile("griddepcontrol.launch_dependents;" ::: "memory");
}

// ---------------------------------------------------------------------------
// k1: y = x @ W1. 64 nodes/block, 256 threads, 2 nodes x 4 cols per thread.
//     x staged UNTRANSPOSED via cp.async; compute reads x as LDS.64 pairs.
//     Writes g_y AND g_agg = y. Block 0 zeroes pool/cnt/done.  (R9 body)
// ---------------------------------------------------------------------------
__global__ __launch_bounds__(256) void k1_gemm_y(
    const float* __restrict__ x, const float* __restrict__ W1)
{
    __shared__ float W1s[D_FEAT * HIDDEN];       // 12 KB
    __shared__ float xs[64 * XS_STRIDE];         // 25.6 KB

    const int tid = threadIdx.x;
    const int node0 = blockIdx.x * 64;
    const uint32_t xs_base  = (uint32_t)__cvta_generic_to_shared(xs);
    const uint32_t w1s_base = (uint32_t)__cvta_generic_to_shared(W1s);

    {
        const float4* W14 = (const float4*)W1;
        for (int i = tid; i < D_FEAT * HIDDEN / 4; i += 256)
            cpa16(w1s_base + i * 16, &W14[i]);
    }
    {
        const float4* x4 = (const float4*)x;
        for (int i = tid; i < 64 * 24; i += 256) {
            const int nl = i / 24, fq = i % 24;
            int node = node0 + nl;
            if (node >= N_NODES) node = N_NODES - 1;   // clamp: data unused
            cpa16(xs_base + (nl * XS_STRIDE + fq * 4) * 4, &x4[node * 24 + fq]);
        }
    }
    if (blockIdx.x == 0) {
        for (int i = tid; i < N_GRAPHS * HIDDEN; i += 256) g_pool[i] = 0.0f;
        if (tid < N_GRAPHS) g_cnt[tid] = 0.0f;
        if (tid == 0) g_done = 0u;
    }
    cpa_commit_wait();
    __syncthreads();

    const int np = tid >> 3;   // 0..31 : node pair
    const int cq = tid & 7;    // 0..7  : col quad
    const int nA = np * 2;
    const int nB = nA + 1;

    unsigned long long a00 = 0ull, a01 = 0ull, a10 = 0ull, a11 = 0ull;

#pragma unroll 8
    for (int f2 = 0; f2 < D_FEAT / 2; f2++) {
        const int f = f2 * 2;
        const float2 xa = *(const float2*)&xs[nA * XS_STRIDE + f];
        const float2 xb = *(const float2*)&xs[nB * XS_STRIDE + f];
        const ulonglong2 w0 = *(const ulonglong2*)&W1s[f * HIDDEN + cq * 4];
        const ulonglong2 w1 = *(const ulonglong2*)&W1s[(f + 1) * HIDDEN + cq * 4];
        unsigned long long d;
        d = pk2(xa.x, xa.x); ffma2(a00, d, w0.x); ffma2(a01, d, w0.y);
        d = pk2(xb.x, xb.x); ffma2(a10, d, w0.x); ffma2(a11, d, w0.y);
        d = pk2(xa.y, xa.y); ffma2(a00, d, w1.x); ffma2(a01, d, w1.y);
        d = pk2(xb.y, xb.y); ffma2(a10, d, w1.x); ffma2(a11, d, w1.y);
    }

    const float2 u00 = up2(a00), u01 = up2(a01), u10 = up2(a10), u11 = up2(a11);
    const int n0 = node0 + nA;

    if (n0 < N_NODES) {
        const float4 r = make_float4(u00.x, u00.y, u01.x, u01.y);
        *(float4*)&g_y[n0 * HIDDEN + cq * 4]   = r;
        *(float4*)&g_agg[n0 * HIDDEN + cq * 4] = r;
    }
    if (n0 + 1 < N_NODES) {
        const float4 r = make_float4(u10.x, u10.y, u11.x, u11.y);
        *(float4*)&g_y[(n0 + 1) * HIDDEN + cq * 4]   = r;
        *(float4*)&g_agg[(n0 + 1) * HIDDEN + cq * 4] = r;
    }
    pdl_trigger();
}

// ---------------------------------------------------------------------------
// k2: edge scatter; 8 lanes/edge, red.global.add.v4.f32.  (R9 body + PDL)
//     Indexes loaded BEFORE the dependency wait -> overlaps k1's tail.
// ---------------------------------------------------------------------------
__global__ __launch_bounds__(256) void k2_scatter(
    const int* __restrict__ edge_index)
{
    const int t   = blockIdx.x * 256 + threadIdx.x;
    const int e   = t >> 3;
    const int sub = t & 7;
    // grid is an exact multiple (800000*8 / 256 = 25000 blocks): no OOB threads

    const int s = __ldg(&edge_index[e]);            // src   (independent of k1)
    const int d = __ldg(&edge_index[N_EDGES + e]);  // dst

    pdl_wait();   // k1's g_y / g_agg now visible

    const float4 v = *reinterpret_cast<const float4*>(&g_y[s * HIDDEN + sub * 4]);
    float* p = &g_agg[d * HIDDEN + sub * 4];
    asm volatile("red.global.add.v4.f32 [%0], {%1, %2, %3, %4};"
                 :: "l"(p), "f"(v.x), "f"(v.y), "f"(v.z), "f"(v.w)
                 : "memory");
    pdl_trigger();
}

// ---------------------------------------------------------------------------
// k3: h = relu(agg+b1); h2 = relu(h@W2+b2); run-length pooling; head.
//     (R9 body + PDL: W2/batch/bias staged before the dependency wait)
// ---------------------------------------------------------------------------
__global__ __launch_bounds__(256) void k3_mlp_pool(
    const float* __restrict__ b1, const float* __restrict__ W2,
    const float* __restrict__ b2, const int* __restrict__ batch,
    const float* __restrict__ Wc, const float* __restrict__ bc,
    float* __restrict__ out)
{
    __shared__ float W2s[HIDDEN * HIDDEN];   // 4 KB
    __shared__ float hs[32 * HS_STRIDE];     // 4.6 KB
    __shared__ float h2s[32 * HS_STRIDE];    // 4.6 KB
    __shared__ int   sb[32];
    __shared__ bool  amLast;

    const int tid = threadIdx.x;
    const int node0 = blockIdx.x * 32;

    // ---- prologue: all reads here are kernel inputs, independent of k2 ----
    {
        const float4* W24 = (const float4*)W2;
        float4* W2s4 = (float4*)W2s;
        for (int i = tid; i < HIDDEN * HIDDEN / 4; i += 256)
            W2s4[i] = W24[i];
    }
    if (tid < 32) {
        const int nd = node0 + tid;
        sb[tid] = (nd < N_NODES) ? batch[nd] : -1;
    }

    const int nl   = tid >> 3;
    const int sub  = tid & 7;
    const int node = node0 + nl;
    const float4 b1v = *(const float4*)&b1[sub * 4];
    const float4 b2v = *(const float4*)&b2[sub * 4];

    pdl_wait();   // k2's g_agg atomics now visible

    // h = relu(agg + b1), staged to smem
    {
        float4 h = make_float4(0.f, 0.f, 0.f, 0.f);
        if (node < N_NODES) {
            const float4 a = *(const float4*)&g_agg[node * HIDDEN + sub * 4];
            h.x = fmaxf(a.x + b1v.x, 0.f);
            h.y = fmaxf(a.y + b1v.y, 0.f);
            h.z = fmaxf(a.z + b1v.z, 0.f);
            h.w = fmaxf(a.w + b1v.w, 0.f);
        }
        *(float4*)&hs[nl * HS_STRIDE + sub * 4] = h;
    }
    __syncthreads();

    // h2 = relu(h @ W2 + b2)
    float4 acc = make_float4(0.f, 0.f, 0.f, 0.f);
#pragma unroll
    for (int kq = 0; kq < 8; kq++) {
        const float4 hv = *(const float4*)&hs[nl * HS_STRIDE + kq * 4];
        {
            const float4 wv = *(const float4*)&W2s[(kq * 4 + 0) * HIDDEN + sub * 4];
            acc.x += hv.x * wv.x; acc.y += hv.x * wv.y; acc.z += hv.x * wv.z; acc.w += hv.x * wv.w;
        }
        {
            const float4 wv = *(const float4*)&W2s[(kq * 4 + 1) * HIDDEN + sub * 4];
            acc.x += hv.y * wv.x; acc.y += hv.y * wv.y; acc.z += hv.y * wv.z; acc.w += hv.y * wv.w;
        }
        {
            const float4 wv = *(const float4*)&W2s[(kq * 4 + 2) * HIDDEN + sub * 4];
            acc.x += hv.z * wv.x; acc.y += hv.z * wv.y; acc.z += hv.z * wv.z; acc.w += hv.z * wv.w;
        }
        {
            const float4 wv = *(const float4*)&W2s[(kq * 4 + 3) * HIDDEN + sub * 4];
            acc.x += hv.w * wv.x; acc.y += hv.w * wv.y; acc.z += hv.w * wv.z; acc.w += hv.w * wv.w;
        }
    }

    {
        acc.x = fmaxf(acc.x + b2v.x, 0.f);
        acc.y = fmaxf(acc.y + b2v.y, 0.f);
        acc.z = fmaxf(acc.z + b2v.z, 0.f);
        acc.w = fmaxf(acc.w + b2v.w, 0.f);
        *(float4*)&h2s[nl * HS_STRIDE + sub * 4] = acc;
    }
    __syncthreads();

    // run-length pooling: batch is sorted -> contiguous graph runs per block.
    if (tid < 8) {
        const int cq = tid;
        float4 pacc = make_float4(0.f, 0.f, 0.f, 0.f);
        float cnt = 0.0f;
        int curg = -1;
        for (int n = 0; n < 32; n++) {
            const int g = sb[n];
            if (g != curg) {
                if (curg >= 0) {
                    float* p = &g_pool[curg * HIDDEN + cq * 4];
                    asm volatile("red.global.add.v4.f32 [%0], {%1, %2, %3, %4};"
                                 :: "l"(p), "f"(pacc.x), "f"(pacc.y), "f"(pacc.z), "f"(pacc.w)
                                 : "memory");
                    if (cq == 0) atomicAdd(&g_cnt[curg], cnt);
                }
                curg = g;
                pacc = make_float4(0.f, 0.f, 0.f, 0.f);
                cnt = 0.0f;
            }
            if (g >= 0) {
                const float4 h = *(const float4*)&h2s[n * HS_STRIDE + cq * 4];
                pacc.x += h.x; pacc.y += h.y; pacc.z += h.z; pacc.w += h.w;
                cnt += 1.0f;
            }
        }
        if (curg >= 0) {
            float* p = &g_pool[curg * HIDDEN + cq * 4];
            asm volatile("red.global.add.v4.f32 [%0], {%1, %2, %3, %4};"
                         :: "l"(p), "f"(pacc.x), "f"(pacc.y), "f"(pacc.z), "f"(pacc.w)
                         : "memory");
            if (cq == 0) atomicAdd(&g_cnt[curg], cnt);
        }
    }

    // -------- last-block epilogue (head GEMV) --------
    __threadfence();
    __syncthreads();
    if (tid == 0)
        amLast = (atomicAdd(&g_done, 1u) == gridDim.x - 1u);
    __syncthreads();

    if (amLast) {
        __threadfence();
        const int g = tid; // 256 threads = 256 graphs
        const float inv = 1.0f / fmaxf(g_cnt[g], 1.0f);
        float o0 = 0.0f, o1 = 0.0f;
#pragma unroll
        for (int k = 0; k < HIDDEN; k++) {
            const float p = g_pool[g * HIDDEN + k] * inv;
            o0 += p * Wc[k * 2 + 0];
            o1 += p * Wc[k * 2 + 1];
        }
        out[g * 2 + 0] = o0 + bc[0];
        out[g * 2 + 1] = o1 + bc[1];
    }
}

// ---------------------------------------------------------------------------
// launch — inputs: x, edge_index, batch, W1, b1, W2, b2, Wc, bc (idx int32)
// k2/k3 launched with ProgrammaticStreamSerialization (PDL overlap).
// ---------------------------------------------------------------------------
extern "C" void kernel_launch(void* const* d_in, const int* in_sizes, int n_in,
                              void* d_out, int out_size)
{
    const float* x    = (const float*)d_in[0];
    const int*   ei   = (const int*)d_in[1];
    const int*   bat  = (const int*)d_in[2];
    const float* W1   = (const float*)d_in[3];
    const float* b1   = (const float*)d_in[4];
    const float* W2   = (const float*)d_in[5];
    const float* b2   = (const float*)d_in[6];
    const float* Wc   = (const float*)d_in[7];
    const float* bc   = (const float*)d_in[8];
    float*       out  = (float*)d_out;

    k1_gemm_y<<<(N_NODES + 63) / 64, 256>>>(x, W1);

    cudaLaunchAttribute attr[1];
    attr[0].id = cudaLaunchAttributeProgrammaticStreamSerialization;
    attr[0].val.programmaticStreamSerializationAllowed = 1;

    {
        cudaLaunchConfig_t cfg = {};
        cfg.gridDim  = dim3((N_EDGES * 8) / 256);
        cfg.blockDim = dim3(256);
        cfg.attrs = attr;
        cfg.numAttrs = 1;
        cudaLaunchKernelEx(&cfg, k2_scatter, ei);
    }
    {
        cudaLaunchConfig_t cfg = {};
        cfg.gridDim  = dim3((N_NODES + 31) / 32);
        cfg.blockDim = dim3(256);
        cfg.attrs = attr;
        cfg.numAttrs = 1;
        cudaLaunchKernelEx(&cfg, k3_mlp_pool, b1, W2, b2, bat, Wc, bc, out);
    }
}

// round 15
// speedup vs baseline: 1.1032x; 1.1032x over previous
#include <cuda_runtime.h>
#include <cstdint>

#define N_NODES  50000
#define N_EDGES  800000
#define N_GRAPHS 256
#define D_FEAT   96
#define HIDDEN   32

#define XS_STRIDE 100   // 96 + 4 pad floats
#define HS_STRIDE 36    // 32 + 4 pad

// Scratch (no cudaMalloc allowed)
__device__ float g_y[N_NODES * HIDDEN];     // x @ W1 (clean copy, k2 gather src)
__device__ float g_agg[N_NODES * HIDDEN];   // accumulator, initialized to y
__device__ float g_pool[N_GRAPHS * HIDDEN]; // per-graph sums
__device__ float g_cnt[N_GRAPHS];           // per-graph node counts
__device__ unsigned g_done;                 // k3 completion counter

// ---------------- f32x2 helpers ----------------
__device__ __forceinline__ unsigned long long pk2(float lo, float hi) {
    unsigned long long r;
    asm("mov.b64 %0, {%1, %2};" : "=l"(r) : "f"(lo), "f"(hi));
    return r;
}
__device__ __forceinline__ void ffma2(unsigned long long& acc,
                                      unsigned long long a, unsigned long long b) {
    asm("fma.rn.f32x2 %0, %1, %2, %0;" : "+l"(acc) : "l"(a), "l"(b));
}
__device__ __forceinline__ float2 up2(unsigned long long v) {
    float2 r;
    asm("mov.b64 {%0, %1}, %2;" : "=f"(r.x), "=f"(r.y) : "l"(v));
    return r;
}
// ---------------- cp.async helpers ----------------
__device__ __forceinline__ void cpa16(uint32_t smem_dst, const void* gmem_src) {
    asm volatile("cp.async.cg.shared.global [%0], [%1], 16;"
                 :: "r"(smem_dst), "l"(gmem_src));
}
__device__ __forceinline__ void cpa_commit_wait() {
    asm volatile("cp.async.commit_group;");
    asm volatile("cp.async.wait_group 0;");
}

// ---------------------------------------------------------------------------
// k1: y = x @ W1. 64 nodes/block, 256 threads, 2 nodes x 4 cols per thread.
//     x staged UNTRANSPOSED via cp.async; compute reads x as LDS.64 pairs.
//     Writes g_y AND g_agg = y. Block 0 zeroes pool/cnt/done.
// ---------------------------------------------------------------------------
__global__ __launch_bounds__(256) void k1_gemm_y(
    const float* __restrict__ x, const float* __restrict__ W1)
{
    __shared__ float W1s[D_FEAT * HIDDEN];       // 12 KB
    __shared__ float xs[64 * XS_STRIDE];         // 25.6 KB

    const int tid = threadIdx.x;
    const int node0 = blockIdx.x * 64;
    const uint32_t xs_base  = (uint32_t)__cvta_generic_to_shared(xs);
    const uint32_t w1s_base = (uint32_t)__cvta_generic_to_shared(W1s);

    {
        const float4* W14 = (const float4*)W1;
        for (int i = tid; i < D_FEAT * HIDDEN / 4; i += 256)
            cpa16(w1s_base + i * 16, &W14[i]);
    }
    {
        const float4* x4 = (const float4*)x;
        for (int i = tid; i < 64 * 24; i += 256) {
            const int nl = i / 24, fq = i % 24;
            int node = node0 + nl;
            if (node >= N_NODES) node = N_NODES - 1;   // clamp: data unused
            cpa16(xs_base + (nl * XS_STRIDE + fq * 4) * 4, &x4[node * 24 + fq]);
        }
    }
    if (blockIdx.x == 0) {
        for (int i = tid; i < N_GRAPHS * HIDDEN; i += 256) g_pool[i] = 0.0f;
        if (tid < N_GRAPHS) g_cnt[tid] = 0.0f;
        if (tid == 0) g_done = 0u;
    }
    cpa_commit_wait();
    __syncthreads();

    const int np = tid >> 3;   // 0..31 : node pair
    const int cq = tid & 7;    // 0..7  : col quad
    const int nA = np * 2;
    const int nB = nA + 1;

    unsigned long long a00 = 0ull, a01 = 0ull, a10 = 0ull, a11 = 0ull;

#pragma unroll 8
    for (int f2 = 0; f2 < D_FEAT / 2; f2++) {
        const int f = f2 * 2;
        const float2 xa = *(const float2*)&xs[nA * XS_STRIDE + f];
        const float2 xb = *(const float2*)&xs[nB * XS_STRIDE + f];
        const ulonglong2 w0 = *(const ulonglong2*)&W1s[f * HIDDEN + cq * 4];
        const ulonglong2 w1 = *(const ulonglong2*)&W1s[(f + 1) * HIDDEN + cq * 4];
        unsigned long long d;
        d = pk2(xa.x, xa.x); ffma2(a00, d, w0.x); ffma2(a01, d, w0.y);
        d = pk2(xb.x, xb.x); ffma2(a10, d, w0.x); ffma2(a11, d, w0.y);
        d = pk2(xa.y, xa.y); ffma2(a00, d, w1.x); ffma2(a01, d, w1.y);
        d = pk2(xb.y, xb.y); ffma2(a10, d, w1.x); ffma2(a11, d, w1.y);
    }

    const float2 u00 = up2(a00), u01 = up2(a01), u10 = up2(a10), u11 = up2(a11);
    const int n0 = node0 + nA;

    if (n0 < N_NODES) {
        const float4 r = make_float4(u00.x, u00.y, u01.x, u01.y);
        *(float4*)&g_y[n0 * HIDDEN + cq * 4]   = r;
        *(float4*)&g_agg[n0 * HIDDEN + cq * 4] = r;
    }
    if (n0 + 1 < N_NODES) {
        const float4 r = make_float4(u10.x, u10.y, u11.x, u11.y);
        *(float4*)&g_y[(n0 + 1) * HIDDEN + cq * 4]   = r;
        *(float4*)&g_agg[(n0 + 1) * HIDDEN + cq * 4] = r;
    }
}

// ---------------------------------------------------------------------------
// k2: edge scatter in 32-dim space; 8 lanes/edge, red.global.add.v4.f32.
//     Same-address LDG across the 8 lanes coalesces to an L1 broadcast.
// ---------------------------------------------------------------------------
__global__ __launch_bounds__(256) void k2_scatter(
    const int* __restrict__ edge_index)
{
    const int t   = blockIdx.x * 256 + threadIdx.x;
    const int e   = t >> 3;
    const int sub = t & 7;
    if (e >= N_EDGES) return;

    const int s = __ldg(&edge_index[e]);            // src
    const int d = __ldg(&edge_index[N_EDGES + e]);  // dst

    const float4 v = *reinterpret_cast<const float4*>(&g_y[s * HIDDEN + sub * 4]);
    float* p = &g_agg[d * HIDDEN + sub * 4];
    asm volatile("red.global.add.v4.f32 [%0], {%1, %2, %3, %4};"
                 :: "l"(p), "f"(v.x), "f"(v.y), "f"(v.z), "f"(v.w)
                 : "memory");
}

// ---------------------------------------------------------------------------
// k3: h = relu(agg+b1) (agg already includes y); h2 = relu(h@W2+b2);
//     run-length smem pooling (batch is sorted); last-block head epilogue.
// ---------------------------------------------------------------------------
__global__ __launch_bounds__(256) void k3_mlp_pool(
    const float* __restrict__ b1, const float* __restrict__ W2,
    const float* __restrict__ b2, const int* __restrict__ batch,
    const float* __restrict__ Wc, const float* __restrict__ bc,
    float* __restrict__ out)
{
    __shared__ float W2s[HIDDEN * HIDDEN];   // 4 KB
    __shared__ float hs[32 * HS_STRIDE];     // 4.6 KB
    __shared__ float h2s[32 * HS_STRIDE];    // 4.6 KB
    __shared__ int   sb[32];
    __shared__ bool  amLast;

    const int tid = threadIdx.x;
    const int node0 = blockIdx.x * 32;

    {
        const float4* W24 = (const float4*)W2;
        float4* W2s4 = (float4*)W2s;
        for (int i = tid; i < HIDDEN * HIDDEN / 4; i += 256)
            W2s4[i] = W24[i];
    }
    if (tid < 32) {
        const int nd = node0 + tid;
        sb[tid] = (nd < N_NODES) ? batch[nd] : -1;
    }

    const int nl   = tid >> 3;
    const int sub  = tid & 7;
    const int node = node0 + nl;

    // h = relu(agg + b1), staged to smem
    {
        float4 h = make_float4(0.f, 0.f, 0.f, 0.f);
        if (node < N_NODES) {
            const float4 a  = *(const float4*)&g_agg[node * HIDDEN + sub * 4];
            const float4 bv = *(const float4*)&b1[sub * 4];
            h.x = fmaxf(a.x + bv.x, 0.f);
            h.y = fmaxf(a.y + bv.y, 0.f);
            h.z = fmaxf(a.z + bv.z, 0.f);
            h.w = fmaxf(a.w + bv.w, 0.f);
        }
        *(float4*)&hs[nl * HS_STRIDE + sub * 4] = h;
    }
    __syncthreads();

    // h2 = relu(h @ W2 + b2)
    float4 acc = make_float4(0.f, 0.f, 0.f, 0.f);
#pragma unroll
    for (int kq = 0; kq < 8; kq++) {
        const float4 hv = *(const float4*)&hs[nl * HS_STRIDE + kq * 4];
        {
            const float4 wv = *(const float4*)&W2s[(kq * 4 + 0) * HIDDEN + sub * 4];
            acc.x += hv.x * wv.x; acc.y += hv.x * wv.y; acc.z += hv.x * wv.z; acc.w += hv.x * wv.w;
        }
        {
            const float4 wv = *(const float4*)&W2s[(kq * 4 + 1) * HIDDEN + sub * 4];
            acc.x += hv.y * wv.x; acc.y += hv.y * wv.y; acc.z += hv.y * wv.z; acc.w += hv.y * wv.w;
        }
        {
            const float4 wv = *(const float4*)&W2s[(kq * 4 + 2) * HIDDEN + sub * 4];
            acc.x += hv.z * wv.x; acc.y += hv.z * wv.y; acc.z += hv.z * wv.z; acc.w += hv.z * wv.w;
        }
        {
            const float4 wv = *(const float4*)&W2s[(kq * 4 + 3) * HIDDEN + sub * 4];
            acc.x += hv.w * wv.x; acc.y += hv.w * wv.y; acc.z += hv.w * wv.z; acc.w += hv.w * wv.w;
        }
    }

    {
        const float4 bv = *(const float4*)&b2[sub * 4];
        acc.x = fmaxf(acc.x + bv.x, 0.f);
        acc.y = fmaxf(acc.y + bv.y, 0.f);
        acc.z = fmaxf(acc.z + bv.z, 0.f);
        acc.w = fmaxf(acc.w + bv.w, 0.f);
        *(float4*)&h2s[nl * HS_STRIDE + sub * 4] = acc;
    }
    __syncthreads();

    // run-length pooling: batch is sorted -> contiguous graph runs per block.
    if (tid < 8) {
        const int cq = tid;
        float4 pacc = make_float4(0.f, 0.f, 0.f, 0.f);
        float cnt = 0.0f;
        int curg = -1;
        for (int n = 0; n < 32; n++) {
            const int g = sb[n];
            if (g != curg) {
                if (curg >= 0) {
                    float* p = &g_pool[curg * HIDDEN + cq * 4];
                    asm volatile("red.global.add.v4.f32 [%0], {%1, %2, %3, %4};"
                                 :: "l"(p), "f"(pacc.x), "f"(pacc.y), "f"(pacc.z), "f"(pacc.w)
                                 : "memory");
                    if (cq == 0) atomicAdd(&g_cnt[curg], cnt);
                }
                curg = g;
                pacc = make_float4(0.f, 0.f, 0.f, 0.f);
                cnt = 0.0f;
            }
            if (g >= 0) {
                const float4 h = *(const float4*)&h2s[n * HS_STRIDE + cq * 4];
                pacc.x += h.x; pacc.y += h.y; pacc.z += h.z; pacc.w += h.w;
                cnt += 1.0f;
            }
        }
        if (curg >= 0) {
            float* p = &g_pool[curg * HIDDEN + cq * 4];
            asm volatile("red.global.add.v4.f32 [%0], {%1, %2, %3, %4};"
                         :: "l"(p), "f"(pacc.x), "f"(pacc.y), "f"(pacc.z), "f"(pacc.w)
                         : "memory");
            if (cq == 0) atomicAdd(&g_cnt[curg], cnt);
        }
    }

    // -------- last-block epilogue (head GEMV) --------
    __threadfence();
    __syncthreads();
    if (tid == 0)
        amLast = (atomicAdd(&g_done, 1u) == gridDim.x - 1u);
    __syncthreads();

    if (amLast) {
        __threadfence();
        const int g = tid; // 256 threads = 256 graphs
        const float inv = 1.0f / fmaxf(g_cnt[g], 1.0f);
        float o0 = 0.0f, o1 = 0.0f;
#pragma unroll
        for (int k = 0; k < HIDDEN; k++) {
            const float p = g_pool[g * HIDDEN + k] * inv;
            o0 += p * Wc[k * 2 + 0];
            o1 += p * Wc[k * 2 + 1];
        }
        out[g * 2 + 0] = o0 + bc[0];
        out[g * 2 + 1] = o1 + bc[1];
    }
}

// ---------------------------------------------------------------------------
// launch — inputs: x, edge_index, batch, W1, b1, W2, b2, Wc, bc (idx int32)
// ---------------------------------------------------------------------------
extern "C" void kernel_launch(void* const* d_in, const int* in_sizes, int n_in,
                              void* d_out, int out_size)
{
    const float* x    = (const float*)d_in[0];
    const int*   ei   = (const int*)d_in[1];
    const int*   bat  = (const int*)d_in[2];
    const float* W1   = (const float*)d_in[3];
    const float* b1   = (const float*)d_in[4];
    const float* W2   = (const float*)d_in[5];
    const float* b2   = (const float*)d_in[6];
    const float* Wc   = (const float*)d_in[7];
    const float* bc   = (const float*)d_in[8];
    float*       out  = (float*)d_out;

    k1_gemm_y<<<(N_NODES + 63) / 64, 256>>>(x, W1);
    k2_scatter<<<(N_EDGES * 8 + 255) / 256, 256>>>(ei);
    k3_mlp_pool<<<(N_NODES + 31) / 32, 256>>>(b1, W2, b2, bat, Wc, bc, out);
}